// round 7
// baseline (speedup 1.0000x reference)
#include <cuda_runtime.h>
#include <cuda_bf16.h>

#define SDIM    4096
#define HDIM    16
#define PDIM    64
#define NDIM    64
#define LCHUNK  64
#define NCHUNK  64
#define NBH     128
#define THRESH  14.0f     // exp(-14)=8e-7; truncation ~1e-5 rel << 1e-3 budget
#define CAP     5         // chunk slots in smem
#define PRE0    (NCHUNK - CAP)   // 59: first speculatively prefetched chunk
#define THREADS 512
#define WIN     1024      // backward A-scan window (16 chunks)

// Dynamic smem layout (floats):
//   xs slots : [CAP][64][64]
//   bs slots : [CAP][64][64]
//   ws       : [SDIM]
#define XS_OFF 0
#define BS_OFF (CAP * 4096)
#define WS_OFF (2 * CAP * 4096)
#define SMEM_BYTES ((2 * CAP * 4096 + SDIM) * 4)

__device__ __forceinline__ void ffma2(unsigned long long& d,
                                      unsigned long long a,
                                      unsigned long long b) {
    asm("fma.rn.f32x2 %0, %1, %2, %0;" : "+l"(d) : "l"(a), "l"(b));
}
__device__ __forceinline__ void fadd2(unsigned long long& d, unsigned long long a) {
    asm("add.rn.f32x2 %0, %0, %1;" : "+l"(d) : "l"(a));
}
__device__ __forceinline__ unsigned long long pack2(float lo, float hi) {
    unsigned long long r;
    asm("mov.b64 %0, {%1, %2};" : "=l"(r) : "f"(lo), "f"(hi));
    return r;
}
__device__ __forceinline__ void unpack2(unsigned long long v, float& lo, float& hi) {
    asm("mov.b64 {%0, %1}, %2;" : "=f"(lo), "=f"(hi) : "l"(v));
}
__device__ __forceinline__ void cp16(float* smem_dst, const float4* gmem_src) {
    unsigned sptr = (unsigned)__cvta_generic_to_shared(smem_dst);
    asm volatile("cp.async.cg.shared.global [%0], [%1], 16;"
                 :: "r"(sptr), "l"(gmem_src) : "memory");
}

union F4U2 { float4 f4; unsigned long long u2[2]; };

__global__ void __launch_bounds__(THREADS)
fused_mamba_kernel(const float* __restrict__ X,
                   const float* __restrict__ A,
                   const float* __restrict__ B,
                   float* __restrict__ out) {
    extern __shared__ float sm[];
    float* ws = sm + WS_OFF;

    __shared__ float warpsum[16];
    __shared__ int   s_start;

    const int bh   = blockIdx.x;
    const int b    = bh >> 4;
    const int h    = bh & 15;
    const int tid  = threadIdx.x;
    const int lane = tid & 31;
    const int warp = tid >> 5;
    const int lh   = tid >> 8;          // l-half group (0/1)
    const int r    = tid & 255;         // r-slot within group
    const int p0   = (r >> 4) << 2;     // 4 p-values
    const int n0   = (r & 15) << 2;     // 4 n-values

    const float4* X4 = (const float4*)X;
    const float4* B4 = (const float4*)B;
    const float*  Ab = A + (long)b * SDIM * HDIM + h;

    if (tid == 0) s_start = NCHUNK - 1;

    // ---- Speculative prefetch: chunks PRE0..63 into slots 0..CAP-1 --------
    #pragma unroll
    for (int s = 0; s < CAP; s++) {
        const long tbase = (long)(b * SDIM + (PRE0 + s) * LCHUNK) * HDIM + h;
        #pragma unroll
        for (int k = 0; k < 2; k++) {
            const int i   = k * THREADS + tid;   // 0..1023
            const int row = i >> 4;
            const int col = i & 15;
            const long g  = (tbase + (long)row * HDIM) * 16 + col;
            cp16(sm + XS_OFF + s * 4096 + row * 64 + col * 4, X4 + g);
            cp16(sm + BS_OFF + s * 4096 + row * 64 + col * 4, B4 + g);
        }
    }
    asm volatile("cp.async.commit_group;" ::: "memory");

    // ---- Phase A: backward windowed A-scan (usually ONE window) -----------
    float suffixBeyond = 0.0f;
    int winEnd = SDIM;
    for (;;) {
        const int winStart = winEnd - WIN;
        const float a0 = Ab[(winStart + 2 * tid)     * HDIM];
        const float a1 = Ab[(winStart + 2 * tid + 1) * HDIM];
        float sc = a0 + a1;
        #pragma unroll
        for (int d = 1; d < 32; d <<= 1) {
            float o = __shfl_up_sync(0xffffffffu, sc, d);
            if (lane >= d) sc += o;
        }
        if (lane == 31) warpsum[warp] = sc;
        __syncthreads();
        if (warp == 0 && lane < 16) {
            float v = warpsum[lane];
            #pragma unroll
            for (int d = 1; d < 16; d <<= 1) {
                float o = __shfl_up_sync(0x0000ffffu, v, d);
                if (lane >= d) v += o;
            }
            warpsum[lane] = v;
        }
        __syncthreads();
        const float off   = (warp > 0) ? warpsum[warp - 1] : 0.0f;
        const float total = warpsum[15];
        const float cs1 = sc + off;
        const float cs0 = cs1 - a1;
        float2 wv;
        wv.x = __expf(total - cs0 + suffixBeyond);
        wv.y = __expf(total - cs1 + suffixBeyond);
        ((float2*)(ws + winStart))[tid] = wv;
        if (lane == 31) {                       // t1 ends a chunk
            const float Uj = total - cs1 + suffixBeyond;
            if (Uj > -THRESH) atomicMin(&s_start, (winStart + 2 * tid + 1) >> 6);
        }
        const float newSuffix = suffixBeyond + total;
        __syncthreads();
        if (winStart == 0 || newSuffix < -THRESH) break;
        suffixBeyond = newSuffix;
        winEnd = winStart;
    }
    const int start = s_start;
    __syncthreads();

    unsigned long long acc[2][4];
    #pragma unroll
    for (int i = 0; i < 2; i++)
        #pragma unroll
        for (int n = 0; n < 4; n++) acc[i][n] = 0ull;

    // ---- Process speculatively prefetched chunks ---------------------------
    asm volatile("cp.async.wait_group 0;" ::: "memory");
    __syncthreads();

    const int s0 = (start > PRE0) ? (start - PRE0) : 0;   // first active slot

    // Scale xs rows by decay weight
    for (int s = s0; s < CAP; s++) {
        float* xsl = sm + XS_OFF + s * 4096;
        const int tw = (PRE0 + s) * LCHUNK;
        #pragma unroll
        for (int k = 0; k < 2; k++) {
            const int i   = k * THREADS + tid;
            const int row = i >> 4;
            const int col = i & 15;
            float4 v = *(float4*)&xsl[row * 64 + col * 4];
            const float w = ws[tw + row];
            v.x *= w; v.y *= w; v.z *= w; v.w *= w;
            *(float4*)&xsl[row * 64 + col * 4] = v;
        }
    }
    __syncthreads();

    // Compute (each group handles half the l-range)
    for (int s = s0; s < CAP; s++) {
        const float* xsl = sm + XS_OFF + s * 4096 + lh * 32 * 64;
        const float* bsl = sm + BS_OFF + s * 4096 + lh * 32 * 64;
        #pragma unroll 4
        for (int l = 0; l < 32; l++) {
            F4U2 xa;
            xa.f4 = *(const float4*)&xsl[l * 64 + p0];
            const float4 bv = *(const float4*)&bsl[l * 64 + n0];
            const unsigned long long b0 = pack2(bv.x, bv.x);
            const unsigned long long b1 = pack2(bv.y, bv.y);
            const unsigned long long b2 = pack2(bv.z, bv.z);
            const unsigned long long b3 = pack2(bv.w, bv.w);
            ffma2(acc[0][0], xa.u2[0], b0);
            ffma2(acc[0][1], xa.u2[0], b1);
            ffma2(acc[0][2], xa.u2[0], b2);
            ffma2(acc[0][3], xa.u2[0], b3);
            ffma2(acc[1][0], xa.u2[1], b0);
            ffma2(acc[1][1], xa.u2[1], b1);
            ffma2(acc[1][2], xa.u2[1], b2);
            ffma2(acc[1][3], xa.u2[1], b3);
        }
    }

    // ---- Fallback: earlier active chunks (practically never taken) --------
    for (int c0 = start; c0 < PRE0; c0 += CAP) {
        const int nc = min(CAP, PRE0 - c0);
        __syncthreads();                       // slots free for reuse
        for (int c = 0; c < nc; c++) {
            const long tbase = (long)(b * SDIM + (c0 + c) * LCHUNK) * HDIM + h;
            #pragma unroll
            for (int k = 0; k < 2; k++) {
                const int i   = k * THREADS + tid;
                const int row = i >> 4;
                const int col = i & 15;
                const long g  = (tbase + (long)row * HDIM) * 16 + col;
                cp16(sm + XS_OFF + c * 4096 + row * 64 + col * 4, X4 + g);
                cp16(sm + BS_OFF + c * 4096 + row * 64 + col * 4, B4 + g);
            }
        }
        asm volatile("cp.async.commit_group;" ::: "memory");
        asm volatile("cp.async.wait_group 0;" ::: "memory");
        __syncthreads();
        for (int c = 0; c < nc; c++) {
            float* xsl = sm + XS_OFF + c * 4096;
            const int tw = (c0 + c) * LCHUNK;
            #pragma unroll
            for (int k = 0; k < 2; k++) {
                const int i   = k * THREADS + tid;
                const int row = i >> 4;
                const int col = i & 15;
                float4 v = *(float4*)&xsl[row * 64 + col * 4];
                const float w = ws[tw + row];
                v.x *= w; v.y *= w; v.z *= w; v.w *= w;
                *(float4*)&xsl[row * 64 + col * 4] = v;
            }
        }
        __syncthreads();
        for (int c = 0; c < nc; c++) {
            const float* xsl = sm + XS_OFF + c * 4096 + lh * 32 * 64;
            const float* bsl = sm + BS_OFF + c * 4096 + lh * 32 * 64;
            #pragma unroll 4
            for (int l = 0; l < 32; l++) {
                F4U2 xa;
                xa.f4 = *(const float4*)&xsl[l * 64 + p0];
                const float4 bv = *(const float4*)&bsl[l * 64 + n0];
                const unsigned long long b0 = pack2(bv.x, bv.x);
                const unsigned long long b1 = pack2(bv.y, bv.y);
                const unsigned long long b2 = pack2(bv.z, bv.z);
                const unsigned long long b3 = pack2(bv.w, bv.w);
                ffma2(acc[0][0], xa.u2[0], b0);
                ffma2(acc[0][1], xa.u2[0], b1);
                ffma2(acc[0][2], xa.u2[0], b2);
                ffma2(acc[0][3], xa.u2[0], b3);
                ffma2(acc[1][0], xa.u2[1], b0);
                ffma2(acc[1][1], xa.u2[1], b1);
                ffma2(acc[1][2], xa.u2[1], b2);
                ffma2(acc[1][3], xa.u2[1], b3);
            }
        }
    }

    // ---- Cross-group reduction (group1 -> smem, group0 adds) --------------
    __syncthreads();
    unsigned long long* buf = (unsigned long long*)sm;   // reuse xs region
    if (lh == 1) {
        #pragma unroll
        for (int q = 0; q < 8; q++)
            buf[q * 256 + r] = acc[q >> 2][q & 3];
    }
    __syncthreads();
    if (lh == 0) {
        #pragma unroll
        for (int q = 0; q < 8; q++)
            fadd2(acc[q >> 2][q & 3], buf[q * 256 + r]);

        // ---- Write out[bh, p, n] ------------------------------------------
        float4* out4 = (float4*)out + (long)bh * PDIM * 16;
        #pragma unroll
        for (int pi = 0; pi < 2; pi++) {
            float4 vlo, vhi;
            unpack2(acc[pi][0], vlo.x, vhi.x);
            unpack2(acc[pi][1], vlo.y, vhi.y);
            unpack2(acc[pi][2], vlo.z, vhi.z);
            unpack2(acc[pi][3], vlo.w, vhi.w);
            out4[(p0 + 2 * pi)     * 16 + (n0 >> 2)] = vlo;
            out4[(p0 + 2 * pi + 1) * 16 + (n0 >> 2)] = vhi;
        }
    }
}

// ---------------------------------------------------------------------------
extern "C" void kernel_launch(void* const* d_in, const int* in_sizes, int n_in,
                              void* d_out, int out_size) {
    const float* X = (const float*)d_in[0];
    const float* A = (const float*)d_in[1];
    const float* B = (const float*)d_in[2];
    float* out = (float*)d_out;

    cudaFuncSetAttribute(fused_mamba_kernel,
                         cudaFuncAttributeMaxDynamicSharedMemorySize,
                         SMEM_BYTES);
    fused_mamba_kernel<<<NBH, THREADS, SMEM_BYTES>>>(X, A, B, out);
}